// round 1
// baseline (speedup 1.0000x reference)
#include <cuda_runtime.h>
#include <math.h>

// Problem constants (from reference: B=16, H=W=96, TAU=0.5)
#define NB   16
#define HW   96
#define NPIX (HW * HW)      // 9216
#define NW   (NPIX / 32)    // 288 bitmask words
#define INF_I (1 << 28)

// Persistent scratch (no allocations allowed in kernel_launch)
__device__ int      g_G[2][NB][NPIX];   // squared column-distance transform per set
__device__ unsigned g_mask[2][NB][NW];  // bitmasks of thresholded sets
__device__ int      g_cnt[2][NB];       // set cardinalities
__device__ int      g_r[NB][2];         // per-image directed results (squared)

// ---------------------------------------------------------------------------
// Phase 1: threshold -> mask bits + counts + 1-D (column) squared EDT.
// One block per (set, image). grid = 32, block = 256.
// ---------------------------------------------------------------------------
__global__ void hd_phase1(const float* __restrict__ pred,
                          const float* __restrict__ targ) {
    int blk = blockIdx.x;
    int set = blk >> 4;         // 0 = prediction, 1 = target
    int img = blk & 15;
    const float* src = (set == 0 ? pred : targ) + img * NPIX;

    __shared__ unsigned char m[NPIX];
    __shared__ int cnt_sh;

    int tid = threadIdx.x;
    if (tid == 0) cnt_sh = 0;
    __syncthreads();

    int local = 0;
    for (int i = tid; i < NPIX; i += blockDim.x) {
        unsigned char v = (src[i] >= 0.5f) ? 1 : 0;
        m[i] = v;
        local += v;
    }
    atomicAdd(&cnt_sh, local);
    __syncthreads();

    // pack bitmask for phase 2 source-set tests
    for (int w = tid; w < NW; w += blockDim.x) {
        unsigned bits = 0;
#pragma unroll
        for (int j = 0; j < 32; j++)
            bits |= ((unsigned)m[w * 32 + j]) << j;
        g_mask[set][img][w] = bits;
    }
    if (tid == 0) g_cnt[set][img] = cnt_sh;

    // column pass: G(y,x) = min over y' in mask of (y-y')^2
    for (int i = tid; i < NPIX; i += blockDim.x) {
        int y = i / HW, x = i % HW;
        int best = INF_I;
#pragma unroll 16
        for (int yp = 0; yp < HW; yp++) {
            int dy = y - yp;
            int d  = dy * dy;
            if (m[yp * HW + x]) best = min(best, d);
        }
        g_G[set][img][i] = best;
    }
}

// ---------------------------------------------------------------------------
// Phase 2: row pass of EDT + masked max over the source set.
// One block per (image, direction). grid = 32, block = 512.
// dir 0: source = prediction set, target = target set (d_ab)
// dir 1: the reverse (d_ba)
// If the target set is empty: result = diameter of the source set (or 0).
// ---------------------------------------------------------------------------
__global__ void hd_phase2() {
    int blk = blockIdx.x;
    int img = blk >> 1, dir = blk & 1;
    int sset = dir, tset = dir ^ 1;

    __shared__ int      G[NPIX];   // 36 KB
    __shared__ unsigned msk[NW];
    __shared__ int      red[512];

    int tid = threadIdx.x, nt = blockDim.x;
    for (int i = tid; i < NPIX; i += nt) G[i] = g_G[tset][img][i];
    for (int w = tid; w < NW;  w += nt) msk[w] = g_mask[sset][img][w];
    __syncthreads();

    int cntT = g_cnt[tset][img];
    int lmax = -1;

    if (cntT > 0) {
        // D^2(p) = min_x' G(y,x') + (x-x')^2, then max over source pixels
        for (int p = tid; p < NPIX; p += nt) {
            int y = p / HW, x = p % HW;
            const int* Gr = &G[y * HW];
            int best = INF_I;
#pragma unroll 16
            for (int xp = 0; xp < HW; xp++) {
                int dx = x - xp;
                best = min(best, Gr[xp] + dx * dx);
            }
            if ((msk[p >> 5] >> (p & 31)) & 1) lmax = max(lmax, best);
        }
    } else {
        // target empty: directed result becomes diameter of source set
        // (never taken for the benchmark inputs; kept for faithfulness)
        for (int p = tid; p < NPIX; p += nt) {
            if (!((msk[p >> 5] >> (p & 31)) & 1)) continue;
            int y = p / HW, x = p % HW;
            for (int q = 0; q < NPIX; q++) {
                if ((msk[q >> 5] >> (q & 31)) & 1) {
                    int dy = y - q / HW;
                    int dx = x - q % HW;
                    lmax = max(lmax, dy * dy + dx * dx);
                }
            }
        }
    }

    red[tid] = lmax;
    __syncthreads();
    for (int s = nt / 2; s > 0; s >>= 1) {
        if (tid < s) red[tid] = max(red[tid], red[tid + s]);
        __syncthreads();
    }
    if (tid == 0) g_r[img][dir] = max(red[0], 0);  // empty source -> 0
}

// ---------------------------------------------------------------------------
// Final: hd_img = sqrt(max(d_ab^2, d_ba^2)); output = mean over batch.
// ---------------------------------------------------------------------------
__global__ void hd_final(float* __restrict__ out) {
    if (threadIdx.x == 0) {
        float s = 0.f;
        for (int i = 0; i < NB; i++) {
            int r = max(g_r[i][0], g_r[i][1]);
            s += sqrtf((float)r);
        }
        out[0] = s * (1.0f / NB);
    }
}

extern "C" void kernel_launch(void* const* d_in, const int* in_sizes, int n_in,
                              void* d_out, int out_size) {
    const float* pred = (const float*)d_in[0];
    const float* targ = (const float*)d_in[1];

    hd_phase1<<<32, 256>>>(pred, targ);
    hd_phase2<<<32, 512>>>();
    hd_final<<<1, 32>>>((float*)d_out);
}

// round 2
// speedup vs baseline: 2.7668x; 2.7668x over previous
#include <cuda_runtime.h>
#include <math.h>

// Problem constants (reference: B=16, H=W=96, TAU=0.5)
#define NB   16
#define HW   96
#define NPIX (HW * HW)      // 9216
#define NW   (NPIX / 32)    // 288 bitmask words
#define INF_I (1 << 28)
#define RPB  12             // rows per phase-2 block
#define NCHUNK (HW / RPB)   // 8

// Persistent scratch (no allocations allowed)
__device__ int      g_G[2][NB][NPIX];   // squared column-EDT per set
__device__ unsigned g_mask[2][NB][NW];  // thresholded-set bitmasks
__device__ int      g_cnt[2][NB];       // set cardinalities
__device__ int      g_r[NB][2];         // per-image directed results (squared)

// ---------------------------------------------------------------------------
// Phase 1: threshold -> bitmask + count + column squared-EDT (two linear
// passes per column, forward & backward run in different warps concurrently).
// One block per (set, image). grid = 32, block = 256.
// ---------------------------------------------------------------------------
__global__ void hd_phase1(const float* __restrict__ pred,
                          const float* __restrict__ targ) {
    int blk = blockIdx.x;
    int set = blk >> 4;
    int img = blk & 15;
    const float* src = (set == 0 ? pred : targ) + img * NPIX;

    __shared__ unsigned msk[NW];
    __shared__ int Gf[NPIX];   // forward-pass (nearest above) distances²
    __shared__ int Gb[NPIX];   // backward-pass distances²
    __shared__ int cnt_sh;

    int tid = threadIdx.x;
    if (tid == 0) cnt_sh = 0;
    __syncthreads();

    // threshold + ballot-pack bitmask
    int local = 0;
#pragma unroll
    for (int it = 0; it < NPIX / 256; it++) {
        int i = it * 256 + tid;
        bool v = src[i] >= 0.5f;
        unsigned b = __ballot_sync(0xffffffffu, v);
        if ((tid & 31) == 0) msk[i >> 5] = b;
        local += v;
    }
    atomicAdd(&cnt_sh, local);

    // zero the result accumulators for phase 2 (stream-ordered before use)
    if (set == 0 && tid == 0) { g_r[img][0] = 0; g_r[img][1] = 0; }
    __syncthreads();

    // column EDT: warp-group A (threads 0..95) forward, group B (128..223)
    // backward, concurrently into separate arrays.
    if (tid < HW) {
        int c = tid;
        int last = -2000;
        for (int y = 0; y < HW; y++) {
            int p = y * HW + c;
            if ((msk[p >> 5] >> (p & 31)) & 1) last = y;
            int d = y - last;           // <= 2095
            Gf[p] = d * d;
        }
    } else if (tid >= 128 && tid < 128 + HW) {
        int c = tid - 128;
        int last = 2000 + HW;
        for (int y = HW - 1; y >= 0; y--) {
            int p = y * HW + c;
            if ((msk[p >> 5] >> (p & 31)) & 1) last = y;
            int d = last - y;
            Gb[p] = d * d;
        }
    }
    __syncthreads();

    // merge + coalesced write-out
    for (int i = tid; i < NPIX; i += 256)
        g_G[set][img][i] = min(Gf[i], Gb[i]);
    for (int w = tid; w < NW; w += 256)
        g_mask[set][img][w] = msk[w];
    if (tid == 0) g_cnt[set][img] = cnt_sh;
}

// ---------------------------------------------------------------------------
// Phase 2: row pass of squared EDT + masked max over source set.
// grid = 16 img * 2 dir * 8 row-chunks = 256 blocks, block = 256.
// ---------------------------------------------------------------------------
__global__ void hd_phase2() {
    int blk   = blockIdx.x;
    int chunk = blk & (NCHUNK - 1);
    int dir   = (blk >> 3) & 1;
    int img   = blk >> 4;
    int sset  = dir, tset = dir ^ 1;
    int y0    = chunk * RPB;

    __shared__ int      G[RPB * HW];   // target-set column-EDT rows
    __shared__ unsigned smask[NW];     // full source bitmask

    int tid = threadIdx.x;
    for (int i = tid; i < RPB * HW; i += 256) G[i] = g_G[tset][img][y0 * HW + i];
    for (int w = tid; w < NW; w += 256)       smask[w] = g_mask[sset][img][w];
    __syncthreads();

    int cntT = g_cnt[tset][img];
    int lmax = 0;

    if (cntT > 0) {
        // D²(y,x) = min_x' G(y,x') + (x-x')² ; max over masked source pixels
        for (int p = tid; p < RPB * HW; p += 256) {
            int row = p / HW, x = p % HW;
            const int* Gr = &G[row * HW];
            int best = INF_I;
#pragma unroll 16
            for (int xp = 0; xp < HW; xp++) {
                int dx = x - xp;
                best = min(best, Gr[xp] + dx * dx);
            }
            int gp = (y0 + row) * HW + x;
            if ((smask[gp >> 5] >> (gp & 31)) & 1) lmax = max(lmax, best);
        }
    } else {
        // target empty: directed result = diameter of source set
        // (never taken for these inputs; kept for faithfulness)
        for (int p = tid; p < RPB * HW; p += 256) {
            int gp = (y0 + p / HW) * HW + (p % HW);
            if (!((smask[gp >> 5] >> (gp & 31)) & 1)) continue;
            int y = gp / HW, x = gp % HW;
            for (int q = 0; q < NPIX; q++) {
                if ((smask[q >> 5] >> (q & 31)) & 1) {
                    int dy = y - q / HW, dx = x - q % HW;
                    lmax = max(lmax, dy * dy + dx * dx);
                }
            }
        }
    }

    // warp max-reduce, then one atomic per warp
#pragma unroll
    for (int off = 16; off > 0; off >>= 1)
        lmax = max(lmax, __shfl_xor_sync(0xffffffffu, lmax, off));
    if ((tid & 31) == 0) atomicMax(&g_r[img][dir], lmax);
}

// ---------------------------------------------------------------------------
// Final: hd = sqrt(max(d_ab², d_ba²)) per image; output = batch mean.
// ---------------------------------------------------------------------------
__global__ void hd_final(float* __restrict__ out) {
    if (threadIdx.x == 0) {
        float s = 0.f;
        for (int i = 0; i < NB; i++) {
            int r = max(g_r[i][0], g_r[i][1]);
            s += sqrtf((float)r);
        }
        out[0] = s * (1.0f / NB);
    }
}

extern "C" void kernel_launch(void* const* d_in, const int* in_sizes, int n_in,
                              void* d_out, int out_size) {
    const float* pred = (const float*)d_in[0];
    const float* targ = (const float*)d_in[1];

    hd_phase1<<<32, 256>>>(pred, targ);
    hd_phase2<<<16 * 2 * NCHUNK, 256>>>();
    hd_final<<<1, 32>>>((float*)d_out);
}

// round 4
// speedup vs baseline: 3.0711x; 1.1100x over previous
#include <cuda_runtime.h>
#include <math.h>

// Problem constants (reference: B=16, H=W=96, TAU=0.5)
#define NB   16
#define HW   96
#define NPIX (HW * HW)      // 9216
#define NW   (NPIX / 32)    // 288 row-major bitmask words
#define NCW  3              // 96-bit column mask words
#define NJ   48             // packed s16x2 pairs per row (96/2)
#define QS   52             // Q-table row stride in words (16B aligned, conflict-free)
#define RPB  12             // rows per phase-2 block
#define NCHUNK (HW / RPB)   // 8
#define G_INF 20000         // > max real D^2 (18050); 20000+9025 < 32767
#define P2_BLOCKS (NB * 2 * NCHUNK)  // 256

// Persistent scratch (no allocations allowed)
__device__ unsigned g_Gp[2][NB][HW * NJ];  // packed s16x2 column-EDT
__device__ unsigned g_mask[2][NB][NW];     // row-major set bitmasks
__device__ int      g_cnt[2][NB];          // set cardinalities
__device__ int      g_r[NB][2];            // directed results (squared)
__device__ unsigned g_done;                // phase-2 completion counter

// per-16-bit-half: min(a+b, c). add.s16x2/min.s16x2 are PTX ISA 8.0 (sm_90+);
// ptxas fuses the pair into VIADDMNMX.
__device__ __forceinline__ unsigned vaddmin16x2(unsigned a, unsigned b, unsigned c) {
    unsigned s, d;
    asm("add.s16x2 %0, %1, %2;" : "=r"(s) : "r"(a), "r"(b));
    asm("min.s16x2 %0, %1, %2;" : "=r"(d) : "r"(s), "r"(c));
    return d;
}

// ---------------------------------------------------------------------------
// Phase 1: threshold -> bitmasks + count + column squared-EDT via bit scans.
// One block per (set, image). grid = 32, block = 256.
// ---------------------------------------------------------------------------
__global__ void hd_phase1(const float* __restrict__ pred,
                          const float* __restrict__ targ) {
    int blk = blockIdx.x, set = blk >> 4, img = blk & 15;
    const float* src = (set == 0 ? pred : targ) + img * NPIX;

    __shared__ unsigned msk[NW];          // row-major bits
    __shared__ unsigned cm[HW * NCW];     // column-major bits
    __shared__ unsigned short Gs[NPIX];   // column EDT (<= 20000)
    __shared__ int cnt_sh;

    int tid = threadIdx.x, lane = tid & 31, wid = tid >> 5;
    if (tid == 0) cnt_sh = 0;
    __syncthreads();

    // threshold + ballot pack + popcount
    int local = 0;
#pragma unroll
    for (int it = 0; it < NPIX / 256; it++) {
        int i = it * 256 + tid;
        bool v = src[i] >= 0.5f;
        unsigned b = __ballot_sync(0xffffffffu, v);
        if (lane == 0) { msk[i >> 5] = b; local += __popc(b); }
    }
    if (lane == 0) atomicAdd(&cnt_sh, local);
    if (set == 0 && tid == 0) { g_r[img][0] = 0; g_r[img][1] = 0; }
    if (blk == 0 && tid == 0) g_done = 0;
    __syncthreads();

    // transpose to column-major bitmasks: one ballot per (column, word)
    for (int t = wid; t < HW * NCW; t += 8) {
        int x = t / 3, w = t - 3 * (t / 3);
        int y = 32 * w + lane;
        unsigned bit = (msk[y * 3 + (x >> 5)] >> (x & 31)) & 1u;
        unsigned cw = __ballot_sync(0xffffffffu, bit);
        if (lane == 0) cm[x * 3 + w] = cw;
    }
    __syncthreads();

    // per-pixel column EDT: nearest set bit in a 96-bit mask via ffs/clz
#pragma unroll
    for (int it = 0; it < NPIX / 256; it++) {
        int i = it * 256 + tid;
        int y = i / HW, x = i - y * HW;
        unsigned c0 = cm[x * 3], c1 = cm[x * 3 + 1], c2 = cm[x * 3 + 2];
        int w = y >> 5, b = y & 31;
        unsigned lowm = (2u << b) - 1u;   // bits 0..b (b=31 -> all ones)
        unsigned him  = 0xffffffffu << b; // bits b..31

        // nearest set bit index >= y (lowest word wins)
        unsigned m0 = (w == 0) ? (c0 & him) : 0u;
        unsigned m1 = (w < 1) ? c1 : ((w == 1) ? (c1 & him) : 0u);
        unsigned m2 = (w < 2) ? c2 : (c2 & him);
        int i2 = m2 ? 64 + __ffs(m2) - 1 : (1 << 14);
        int i1 = m1 ? 32 + __ffs(m1) - 1 : i2;
        int lo = m0 ? __ffs(m0) - 1 : i1;
        int dd = lo - y;

        // nearest set bit index <= y (highest word wins)
        unsigned h0 = (w == 0) ? (c0 & lowm) : c0;
        unsigned h1 = (w < 1) ? 0u : ((w == 1) ? (c1 & lowm) : c1);
        unsigned h2 = (w < 2) ? 0u : (c2 & lowm);
        int j0 = h0 ? 31 - __clz(h0) : -(1 << 14);
        int j1 = h1 ? 63 - __clz(h1) : j0;
        int hi = h2 ? 95 - __clz(h2) : j1;
        int du = y - hi;

        int d = min(dd, du);
        Gs[i] = (unsigned short)min(d * d, G_INF);
    }
    __syncthreads();

    // pack pairs and write out
    for (int idx = tid; idx < HW * NJ; idx += 256) {
        int y = idx / NJ, j = idx - y * NJ;
        unsigned lo = Gs[y * HW + 2 * j];
        unsigned hi = Gs[y * HW + 2 * j + 1];
        g_Gp[set][img][idx] = lo | (hi << 16);
    }
    for (int w2 = tid; w2 < NW; w2 += 256) g_mask[set][img][w2] = msk[w2];
    if (tid == 0) g_cnt[set][img] = cnt_sh;
}

// ---------------------------------------------------------------------------
// Phase 2: row pass via packed add/min s16x2 + masked max + fused final.
// grid = 16 img * 2 dir * 8 chunks = 256, block = 384 (12 warps, 1 warp/row).
// ---------------------------------------------------------------------------
__global__ void hd_phase2(float* __restrict__ out) {
    int blk = blockIdx.x;
    int chunk = blk & (NCHUNK - 1), dir = (blk >> 3) & 1, img = blk >> 4;
    int sset = dir, tset = dir ^ 1, y0 = chunk * RPB;

    __shared__ unsigned Q[HW * QS];      // packed ((x-2j)^2,(x-2j-1)^2)
    __shared__ unsigned Gp[RPB * NJ];    // packed target column-EDT rows
    __shared__ unsigned smask[NW];       // source bitmask
    __shared__ int last_flag;

    int tid = threadIdx.x;
    // build Q (identical for all blocks, cheap: 12 iters)
    for (int idx = tid; idx < HW * NJ; idx += 384) {
        int x = idx / NJ, j = idx - x * NJ;
        int u = x - 2 * j, v = u - 1;
        Q[x * QS + j] = (unsigned)(u * u) | ((unsigned)(v * v) << 16);
    }
    for (int i = tid; i < RPB * NJ; i += 384) Gp[i] = g_Gp[tset][img][y0 * NJ + i];
    for (int w = tid; w < NW; w += 384)       smask[w] = g_mask[sset][img][w];
    __syncthreads();

    int cntT = g_cnt[tset][img];
    int lmax = 0;

    if (cntT > 0) {
        int lane = tid & 31, r = tid >> 5;     // warp r -> row y0+r
        int y = y0 + r;
        const uint4* G4 = (const uint4*)&Gp[r * NJ];
        int x0 = lane, x1 = lane + 32, x2 = lane + 64;
        const uint4* Q0 = (const uint4*)&Q[x0 * QS];
        const uint4* Q1 = (const uint4*)&Q[x1 * QS];
        const uint4* Q2 = (const uint4*)&Q[x2 * QS];
        unsigned b0 = 0x7FFF7FFFu, b1 = 0x7FFF7FFFu, b2 = 0x7FFF7FFFu;
#pragma unroll
        for (int j4 = 0; j4 < NJ / 4; j4++) {
            uint4 g  = G4[j4];           // broadcast within warp
            uint4 q0 = Q0[j4];
            uint4 q1 = Q1[j4];
            uint4 q2 = Q2[j4];
            b0 = vaddmin16x2(g.x, q0.x, b0); b0 = vaddmin16x2(g.y, q0.y, b0);
            b0 = vaddmin16x2(g.z, q0.z, b0); b0 = vaddmin16x2(g.w, q0.w, b0);
            b1 = vaddmin16x2(g.x, q1.x, b1); b1 = vaddmin16x2(g.y, q1.y, b1);
            b1 = vaddmin16x2(g.z, q1.z, b1); b1 = vaddmin16x2(g.w, q1.w, b1);
            b2 = vaddmin16x2(g.x, q2.x, b2); b2 = vaddmin16x2(g.y, q2.y, b2);
            b2 = vaddmin16x2(g.z, q2.z, b2); b2 = vaddmin16x2(g.w, q2.w, b2);
        }
        int e0 = min(b0 & 0xFFFFu, b0 >> 16);
        int e1 = min(b1 & 0xFFFFu, b1 >> 16);
        int e2 = min(b2 & 0xFFFFu, b2 >> 16);
        int p0 = y * HW + x0, p1 = y * HW + x1, p2 = y * HW + x2;
        if ((smask[p0 >> 5] >> (p0 & 31)) & 1) lmax = max(lmax, e0);
        if ((smask[p1 >> 5] >> (p1 & 31)) & 1) lmax = max(lmax, e1);
        if ((smask[p2 >> 5] >> (p2 & 31)) & 1) lmax = max(lmax, e2);
    } else {
        // target empty: directed result = diameter of source set
        // (never taken for these inputs; kept for faithfulness)
        for (int p = tid; p < RPB * HW; p += 384) {
            int gp = (y0 + p / HW) * HW + (p % HW);
            if (!((smask[gp >> 5] >> (gp & 31)) & 1)) continue;
            int y = gp / HW, x = gp % HW;
            for (int q = 0; q < NPIX; q++) {
                if ((smask[q >> 5] >> (q & 31)) & 1) {
                    int dy = y - q / HW, dx = x - q % HW;
                    lmax = max(lmax, dy * dy + dx * dx);
                }
            }
        }
    }

    // warp max-reduce, one atomic per warp
#pragma unroll
    for (int off = 16; off > 0; off >>= 1)
        lmax = max(lmax, __shfl_xor_sync(0xffffffffu, lmax, off));
    if ((tid & 31) == 0) atomicMax(&g_r[img][dir], lmax);

    // fused final: last block computes the batch mean (threadfence-reduction)
    __syncthreads();
    if (tid == 0) {
        __threadfence();
        unsigned t = atomicAdd(&g_done, 1u);
        last_flag = (t == P2_BLOCKS - 1);
    }
    __syncthreads();
    if (last_flag && tid == 0) {
        __threadfence();
        float s = 0.f;
        for (int i = 0; i < NB; i++)
            s += sqrtf((float)max(g_r[i][0], g_r[i][1]));
        out[0] = s * (1.0f / NB);
    }
}

extern "C" void kernel_launch(void* const* d_in, const int* in_sizes, int n_in,
                              void* d_out, int out_size) {
    const float* pred = (const float*)d_in[0];
    const float* targ = (const float*)d_in[1];

    hd_phase1<<<32, 256>>>(pred, targ);
    hd_phase2<<<P2_BLOCKS, 384>>>((float*)d_out);
}

// round 5
// speedup vs baseline: 3.3925x; 1.1047x over previous
#include <cuda_runtime.h>
#include <math.h>

// Problem constants (reference: B=16, H=W=96, TAU=0.5)
#define NB    16
#define HW    96
#define NPIX  (HW * HW)        // 9216
#define NCW   3                // 96-bit column-mask words
#define RPB   4                // rows per main-kernel block
#define NCHUNK (HW / RPB)      // 24
#define G_INF 20000            // > max real D^2 (18050); +9025 < 32767
#define MAIN_BLOCKS (NB * 2 * NCHUNK)  // 768

// Persistent scratch (no allocations allowed)
__device__ unsigned g_cm[2][NB][HW * NCW];  // column-major set bitmasks
__device__ int      g_cntp[2][NB][3];       // partial set counts (per word-row)
__device__ int      g_r[NB][2];             // directed results (squared)
__device__ unsigned g_done;                 // main-kernel completion counter

// ---------------------------------------------------------------------------
// Kernel A: threshold -> column-major bitmasks + partial counts.
// grid = 2 sets * 16 imgs * 3 word-rows = 96, block = 256.
// Block (set,img,w) handles rows [32w, 32w+32).
// ---------------------------------------------------------------------------
__global__ void hd_masks(const float* __restrict__ pred,
                         const float* __restrict__ targ) {
    int blk = blockIdx.x;
    int w = blk % 3, img = (blk / 3) & 15, set = blk / 48;
    const float* src = (set ? targ : pred) + img * NPIX + (w * 32) * HW;

    __shared__ unsigned rm[32 * 3];   // row-major ballot words for 32 rows
    __shared__ int cnt_sh;

    int tid = threadIdx.x, lane = tid & 31, wid = tid >> 5;
    if (tid == 0) cnt_sh = 0;
    if (blk == 0 && tid == 0) g_done = 0;
    if (blk < 2 * NB && tid == 0) ((int*)g_r)[blk] = 0;   // zero 32 result ints
    __syncthreads();

    // stage 1: coalesced row-major ballots (warp wid covers 4 rows)
    int local = 0;
#pragma unroll
    for (int k = 0; k < 4; k++) {
        int r = wid * 4 + k;
#pragma unroll
        for (int c = 0; c < 3; c++) {
            bool v = src[r * HW + c * 32 + lane] >= 0.5f;
            unsigned bal = __ballot_sync(0xffffffffu, v);
            if (lane == 0) { rm[r * 3 + c] = bal; local += __popc(bal); }
        }
    }
    if (lane == 0) atomicAdd(&cnt_sh, local);
    __syncthreads();

    // stage 2: transpose ballots -> column-major words (lane = local row)
#pragma unroll
    for (int k = 0; k < 12; k++) {
        int x = wid * 12 + k;
        unsigned bit = (rm[lane * 3 + (x >> 5)] >> (x & 31)) & 1u;
        unsigned cw = __ballot_sync(0xffffffffu, bit);
        if (lane == 0) g_cm[set][img][x * 3 + w] = cw;
    }
    if (tid == 0) g_cntp[set][img][w] = cnt_sh;
}

// ---------------------------------------------------------------------------
// Kernel B: per-block fused column-EDT (ffs/clz) + packed s16x2 row pass
// + masked max + fused final reduction.
// grid = 16 img * 2 dir * 24 chunks = 768, block = 384
// (12 warps = 4 rows x 3 column-thirds, one output pixel per lane).
// ---------------------------------------------------------------------------
__global__ void hd_main(float* __restrict__ out) {
    int blk = blockIdx.x;
    int chunk = blk % NCHUNK, dir = (blk / NCHUNK) & 1, img = blk / (2 * NCHUNK);
    int sset = dir, tset = dir ^ 1;
    int y0 = chunk * RPB;

    __shared__ unsigned tcm[HW * NCW];   // target column masks
    __shared__ unsigned scm[HW * NCW];   // source column masks
    __shared__ uint4    hs4[RPB * 12];   // h = G + j^2 packed s16x2, 4 rows
    __shared__ int last_flag;
    unsigned short* hs = (unsigned short*)hs4;

    int tid = threadIdx.x;
    if (tid < HW * NCW) tcm[tid] = g_cm[tset][img][tid];
    if (tid >= 96)      scm[tid - 96] = g_cm[sset][img][tid - 96];
    __syncthreads();

    // column EDT for the block's RPB rows: 1 pixel/thread via bit scans
    {
        int r = tid / HW, x = tid - r * HW;
        int y = y0 + r;
        unsigned c0 = tcm[x * 3], c1 = tcm[x * 3 + 1], c2 = tcm[x * 3 + 2];
        int w = y >> 5, b = y & 31;
        unsigned lowm = (2u << b) - 1u;
        unsigned him  = 0xffffffffu << b;

        unsigned m0 = (w == 0) ? (c0 & him) : 0u;
        unsigned m1 = (w < 1) ? c1 : ((w == 1) ? (c1 & him) : 0u);
        unsigned m2 = (w < 2) ? c2 : (c2 & him);
        int i2 = m2 ? 64 + __ffs(m2) - 1 : (1 << 14);
        int i1 = m1 ? 32 + __ffs(m1) - 1 : i2;
        int lo = m0 ? __ffs(m0) - 1 : i1;
        int dd = lo - y;

        unsigned h0 = (w == 0) ? (c0 & lowm) : c0;
        unsigned h1 = (w < 1) ? 0u : ((w == 1) ? (c1 & lowm) : c1);
        unsigned h2 = (w < 2) ? 0u : (c2 & lowm);
        int j0 = h0 ? 31 - __clz(h0) : -(1 << 14);
        int j1 = h1 ? 63 - __clz(h1) : j0;
        int hi = h2 ? 95 - __clz(h2) : j1;
        int du = y - hi;

        int d = min(dd, du);
        int g = min(d * d, G_INF);
        hs[r * HW + x] = (unsigned short)(g + x * x);  // fold j^2 into h
    }
    __syncthreads();

    int cntT = g_cntp[tset][img][0] + g_cntp[tset][img][1] + g_cntp[tset][img][2];
    int lmax = 0;

    if (cntT > 0) {
        int lane = tid & 31, wrp = tid >> 5;
        int r = wrp & 3, third = wrp >> 2;     // 4 rows x 3 thirds
        int y = y0 + r;
        int x = third * 32 + lane;
        const uint4* H = &hs4[r * 12];

        // D^2(x) = x^2 + min_j (h_j - 2xj); -2xj tracked incrementally packed.
        int s = -4 * x;
        unsigned incp = ((unsigned)s & 0xFFFFu) | ((unsigned)s << 16);
        unsigned wreg = ((unsigned)(-2 * x)) << 16;   // (0, -2x)
        unsigned b = 0x7FFF7FFFu;
#pragma unroll
        for (int i = 0; i < 12; i++) {
            uint4 hv = H[i];                          // broadcast LDS.128
            b = __viaddmin_s16x2(hv.x, wreg, b); wreg = __vadd2(wreg, incp);
            b = __viaddmin_s16x2(hv.y, wreg, b); wreg = __vadd2(wreg, incp);
            b = __viaddmin_s16x2(hv.z, wreg, b); wreg = __vadd2(wreg, incp);
            b = __viaddmin_s16x2(hv.w, wreg, b); wreg = __vadd2(wreg, incp);
        }
        int blo = (int)(short)(b & 0xFFFFu);
        int bhi = (int)(short)(b >> 16);
        int e = x * x + min(blo, bhi);

        // masked max over source set (column-major bit test)
        if ((scm[x * 3 + (y >> 5)] >> (y & 31)) & 1) lmax = e;
    } else {
        // target empty: directed result = diameter of source set
        // (never taken for these inputs; kept for faithfulness)
        for (int p = tid; p < RPB * HW; p += 384) {
            int y = y0 + p / HW, x = p % HW;
            if (!((scm[x * 3 + (y >> 5)] >> (y & 31)) & 1)) continue;
            for (int q = 0; q < NPIX; q++) {
                int qy = q / HW, qx = q - qy * HW;
                if ((scm[qx * 3 + (qy >> 5)] >> (qy & 31)) & 1) {
                    int dy = y - qy, dx = x - qx;
                    lmax = max(lmax, dy * dy + dx * dx);
                }
            }
        }
    }

    // warp max-reduce, one atomic per warp
#pragma unroll
    for (int off = 16; off > 0; off >>= 1)
        lmax = max(lmax, __shfl_xor_sync(0xffffffffu, lmax, off));
    if ((tid & 31) == 0) atomicMax(&g_r[img][dir], lmax);

    // fused final: last block computes the batch mean
    __syncthreads();
    if (tid == 0) {
        __threadfence();
        unsigned t = atomicAdd(&g_done, 1u);
        last_flag = (t == MAIN_BLOCKS - 1);
    }
    __syncthreads();
    if (last_flag && tid == 0) {
        __threadfence();
        float sum = 0.f;
        for (int i = 0; i < NB; i++)
            sum += sqrtf((float)max(g_r[i][0], g_r[i][1]));
        out[0] = sum * (1.0f / NB);
    }
}

extern "C" void kernel_launch(void* const* d_in, const int* in_sizes, int n_in,
                              void* d_out, int out_size) {
    const float* pred = (const float*)d_in[0];
    const float* targ = (const float*)d_in[1];

    hd_masks<<<96, 256>>>(pred, targ);
    hd_main<<<MAIN_BLOCKS, 384>>>((float*)d_out);
}

// round 6
// speedup vs baseline: 3.8535x; 1.1359x over previous
#include <cuda_runtime.h>
#include <math.h>

// Problem constants (reference: B=16, H=W=96, TAU=0.5)
#define NB    16
#define HW    96
#define NPIX  (HW * HW)        // 9216
#define NCW   3                // 96-bit column-mask words
#define RPB   8                // rows per main-kernel block
#define NCHUNK (HW / RPB)      // 12
#define G_INF 20000            // > max real D^2 (18050); +9025 < 32767
#define MAIN_BLOCKS (NB * 2 * NCHUNK)  // 384

// Persistent scratch (no allocations allowed)
__device__ unsigned g_cm[2][NB][HW * NCW];  // column-major set bitmasks
__device__ int      g_cntp[2][NB][3];       // partial set counts
__device__ int      g_r[NB][2];             // directed results (squared)
__device__ unsigned g_done;                 // completion counter

// ---------------------------------------------------------------------------
// Kernel A: threshold -> column-major bitmasks + partial counts.
// grid = 2 sets * 16 imgs * 3 word-rows = 96, block = 256.
// ---------------------------------------------------------------------------
__global__ void hd_masks(const float* __restrict__ pred,
                         const float* __restrict__ targ) {
    int blk = blockIdx.x;
    int w = blk % 3, img = (blk / 3) & 15, set = blk / 48;
    const float* src = (set ? targ : pred) + img * NPIX + (w * 32) * HW;

    __shared__ unsigned rm[32 * 3];
    __shared__ int cnt_sh;

    int tid = threadIdx.x, lane = tid & 31, wid = tid >> 5;
    if (tid == 0) cnt_sh = 0;
    if (blk == 0 && tid == 0) g_done = 0;
    if (blk < 2 * NB && tid == 0) ((int*)g_r)[blk] = 0;
    __syncthreads();

    int local = 0;
#pragma unroll
    for (int k = 0; k < 4; k++) {
        int r = wid * 4 + k;
#pragma unroll
        for (int c = 0; c < 3; c++) {
            bool v = src[r * HW + c * 32 + lane] >= 0.5f;
            unsigned bal = __ballot_sync(0xffffffffu, v);
            if (lane == 0) { rm[r * 3 + c] = bal; local += __popc(bal); }
        }
    }
    if (lane == 0) atomicAdd(&cnt_sh, local);
    __syncthreads();

#pragma unroll
    for (int k = 0; k < 12; k++) {
        int x = wid * 12 + k;
        unsigned bit = (rm[lane * 3 + (x >> 5)] >> (x & 31)) & 1u;
        unsigned cw = __ballot_sync(0xffffffffu, bit);
        if (lane == 0) g_cm[set][img][x * 3 + w] = cw;
    }
    if (tid == 0) g_cntp[set][img][w] = cnt_sh;
}

// ---------------------------------------------------------------------------
// Kernel B: fused column-EDT (ffs/clz) + packed s16x2 row pass with 4-way
// split accumulator chains, 2 units per warp, block-level reduce.
// grid = 16 img * 2 dir * 12 chunks = 384, block = 384 (single wave).
// ---------------------------------------------------------------------------
__global__ void __launch_bounds__(384, 3) hd_main(float* __restrict__ out) {
    int blk = blockIdx.x;
    int chunk = blk % NCHUNK, dir = (blk / NCHUNK) & 1, img = blk / (2 * NCHUNK);
    int sset = dir, tset = dir ^ 1;
    int y0 = chunk * RPB;

    __shared__ unsigned tcm[HW * NCW];   // target column masks
    __shared__ unsigned scm[HW * NCW];   // source column masks
    __shared__ uint4    hs4[RPB * 12];   // h = G + j^2 packed s16x2, 8 rows
    __shared__ int      red[12];
    __shared__ int      last_flag;
    unsigned short* hs = (unsigned short*)hs4;

    int tid = threadIdx.x;
    if (tid < HW * NCW) tcm[tid] = g_cm[tset][img][tid];
    else if (tid - 288 < HW * NCW) scm[tid - 288] = g_cm[sset][img][tid - 288];
    // remaining 288 scm words:
    if (tid < 192) scm[96 + tid] = g_cm[sset][img][96 + tid];
    __syncthreads();

    // column EDT for the block's 8 rows: 2 pixels per thread via bit scans
#pragma unroll
    for (int k = 0; k < 2; k++) {
        int p = tid + k * 384;
        int r = p / HW, x = p - r * HW;
        int y = y0 + r;
        unsigned c0 = tcm[x * 3], c1 = tcm[x * 3 + 1], c2 = tcm[x * 3 + 2];
        int w = y >> 5, b = y & 31;
        unsigned lowm = (2u << b) - 1u;
        unsigned him  = 0xffffffffu << b;

        unsigned m0 = (w == 0) ? (c0 & him) : 0u;
        unsigned m1 = (w < 1) ? c1 : ((w == 1) ? (c1 & him) : 0u);
        unsigned m2 = (w < 2) ? c2 : (c2 & him);
        int i2 = m2 ? 64 + __ffs(m2) - 1 : (1 << 14);
        int i1 = m1 ? 32 + __ffs(m1) - 1 : i2;
        int lo = m0 ? __ffs(m0) - 1 : i1;
        int dd = lo - y;

        unsigned h0 = (w == 0) ? (c0 & lowm) : c0;
        unsigned h1 = (w < 1) ? 0u : ((w == 1) ? (c1 & lowm) : c1);
        unsigned h2 = (w < 2) ? 0u : (c2 & lowm);
        int j0 = h0 ? 31 - __clz(h0) : -(1 << 14);
        int j1 = h1 ? 63 - __clz(h1) : j0;
        int hi = h2 ? 95 - __clz(h2) : j1;
        int du = y - hi;

        int d = min(dd, du);
        int g = min(d * d, G_INF);
        hs[r * HW + x] = (unsigned short)(g + x * x);   // fold j^2 in
    }
    __syncthreads();

    int cntT = g_cntp[tset][img][0] + g_cntp[tset][img][1] + g_cntp[tset][img][2];
    int lmax = 0;
    int lane = tid & 31, wrp = tid >> 5;

    if (cntT > 0) {
        // two (row, third) units per warp: u = wrp and wrp + 12
#pragma unroll
        for (int uu = 0; uu < 2; uu++) {
            int u = wrp + uu * 12;        // 0..23
            int r = u >> 2 ? u / 3 : u / 3;  // row = u / 3 (0..7)
            r = u / 3;
            int third = u - r * 3;
            int y = y0 + r;
            int x = third * 32 + lane;
            const uint4* H = &hs4[r * 12];

            // D^2(x) = x^2 + min_j (h_j - 2xj), 4 independent packed chains
            int s  = -4 * x;              // per-pair step
            int s4 = -16 * x;             // per-iteration step (4 pairs)
            unsigned incp4 = ((unsigned)s4 & 0xFFFFu) | ((unsigned)s4 << 16);
            unsigned w0 = ((unsigned)(0)        & 0xFFFFu) | ((unsigned)(-2 * x)         << 16);
            unsigned w1 = ((unsigned)(s)        & 0xFFFFu) | ((unsigned)(s - 2 * x)      << 16);
            unsigned w2 = ((unsigned)(2 * s)    & 0xFFFFu) | ((unsigned)(2 * s - 2 * x)  << 16);
            unsigned w3 = ((unsigned)(3 * s)    & 0xFFFFu) | ((unsigned)(3 * s - 2 * x)  << 16);
            unsigned b0 = 0x7FFF7FFFu, b1 = 0x7FFF7FFFu;
            unsigned b2 = 0x7FFF7FFFu, b3 = 0x7FFF7FFFu;
#pragma unroll
            for (int i = 0; i < 12; i++) {
                uint4 hv = H[i];                          // broadcast LDS.128
                b0 = __viaddmin_s16x2(hv.x, w0, b0); w0 = __vadd2(w0, incp4);
                b1 = __viaddmin_s16x2(hv.y, w1, b1); w1 = __vadd2(w1, incp4);
                b2 = __viaddmin_s16x2(hv.z, w2, b2); w2 = __vadd2(w2, incp4);
                b3 = __viaddmin_s16x2(hv.w, w3, b3); w3 = __vadd2(w3, incp4);
            }
            unsigned bm = __vmins2(__vmins2(b0, b1), __vmins2(b2, b3));
            int blo = (int)(short)(bm & 0xFFFFu);
            int bhi = (int)(short)(bm >> 16);
            int e = x * x + min(blo, bhi);

            if ((scm[x * 3 + (y >> 5)] >> (y & 31)) & 1) lmax = max(lmax, e);
        }
    } else {
        // target empty: directed result = diameter of source set
        // (never taken for these inputs; kept for faithfulness)
        for (int p = tid; p < RPB * HW; p += 384) {
            int y = y0 + p / HW, x = p % HW;
            if (!((scm[x * 3 + (y >> 5)] >> (y & 31)) & 1)) continue;
            for (int q = 0; q < NPIX; q++) {
                int qy = q / HW, qx = q - qy * HW;
                if ((scm[qx * 3 + (qy >> 5)] >> (qy & 31)) & 1) {
                    int dy = y - qy, dx = x - qx;
                    lmax = max(lmax, dy * dy + dx * dx);
                }
            }
        }
    }

    // warp reduce -> shared -> single atomic per block
#pragma unroll
    for (int off = 16; off > 0; off >>= 1)
        lmax = max(lmax, __shfl_xor_sync(0xffffffffu, lmax, off));
    if (lane == 0) red[wrp] = lmax;
    __syncthreads();
    if (wrp == 0) {
        int v = (lane < 12) ? red[lane] : 0;
#pragma unroll
        for (int off = 16; off > 0; off >>= 1)
            v = max(v, __shfl_xor_sync(0xffffffffu, v, off));
        if (lane == 0) atomicMax(&g_r[img][dir], v);
    }

    // fused final: last block computes the batch mean
    __syncthreads();
    if (tid == 0) {
        __threadfence();
        unsigned t = atomicAdd(&g_done, 1u);
        last_flag = (t == MAIN_BLOCKS - 1);
    }
    __syncthreads();
    if (last_flag && tid == 0) {
        __threadfence();
        float sum = 0.f;
        for (int i = 0; i < NB; i++)
            sum += sqrtf((float)max(g_r[i][0], g_r[i][1]));
        out[0] = sum * (1.0f / NB);
    }
}

extern "C" void kernel_launch(void* const* d_in, const int* in_sizes, int n_in,
                              void* d_out, int out_size) {
    const float* pred = (const float*)d_in[0];
    const float* targ = (const float*)d_in[1];

    hd_masks<<<96, 256>>>(pred, targ);
    hd_main<<<MAIN_BLOCKS, 384>>>((float*)d_out);
}

// round 7
// speedup vs baseline: 4.6066x; 1.1954x over previous
#include <cuda_runtime.h>
#include <math.h>

// Problem constants (reference: B=16, H=W=96, TAU=0.5)
#define NB    16
#define HW    96
#define NPIX  (HW * HW)        // 9216
#define NCW   3                // 96-bit column-mask words
#define RPB   8                // rows per main-kernel block
#define NCHUNK (HW / RPB)      // 12
#define G_INF 20000            // > max real D^2 (18050)
#define MAIN_BLOCKS (NB * 2 * NCHUNK)  // 384

// Persistent scratch (no allocations allowed)
__device__ unsigned g_cm[2][NB][HW * NCW];  // column-major set bitmasks
__device__ int      g_cntp[2][NB][3];       // partial set counts
__device__ int      g_r[NB][2];             // directed results (squared)
__device__ unsigned g_done;                 // completion counter

// ---------------------------------------------------------------------------
// Kernel A: threshold -> column-major bitmasks + partial counts.
// grid = 2 sets * 16 imgs * 3 word-rows = 96, block = 256.
// ---------------------------------------------------------------------------
__global__ void hd_masks(const float* __restrict__ pred,
                         const float* __restrict__ targ) {
    int blk = blockIdx.x;
    int w = blk % 3, img = (blk / 3) & 15, set = blk / 48;
    const float* src = (set ? targ : pred) + img * NPIX + (w * 32) * HW;

    __shared__ unsigned rm[32 * 3];
    __shared__ int cnt_sh;

    int tid = threadIdx.x, lane = tid & 31, wid = tid >> 5;
    if (tid == 0) cnt_sh = 0;
    if (blk == 0 && tid == 0) g_done = 0;
    if (blk < 2 * NB && tid == 0) ((int*)g_r)[blk] = 0;
    __syncthreads();

    int local = 0;
#pragma unroll
    for (int k = 0; k < 4; k++) {
        int r = wid * 4 + k;
#pragma unroll
        for (int c = 0; c < 3; c++) {
            bool v = src[r * HW + c * 32 + lane] >= 0.5f;
            unsigned bal = __ballot_sync(0xffffffffu, v);
            if (lane == 0) { rm[r * 3 + c] = bal; local += __popc(bal); }
        }
    }
    if (lane == 0) atomicAdd(&cnt_sh, local);
    __syncthreads();

#pragma unroll
    for (int k = 0; k < 12; k++) {
        int x = wid * 12 + k;
        unsigned bit = (rm[lane * 3 + (x >> 5)] >> (x & 31)) & 1u;
        unsigned cw = __ballot_sync(0xffffffffu, bit);
        if (lane == 0) g_cm[set][img][x * 3 + w] = cw;
    }
    if (tid == 0) g_cntp[set][img][w] = cnt_sh;
}

// ---------------------------------------------------------------------------
// Kernel B: fused column-EDT (ffs/clz) + PRUNED windowed row pass.
// Exactness: (a) stopping the window at k^2 >= best is lossless since
// G >= 0 implies all farther candidates are >= best; (b) skipping pixels
// with G[x] <= running max is lossless since D^2(x) <= G[x].
// grid = 16 img * 2 dir * 12 chunks = 384, block = 384 (single wave).
// ---------------------------------------------------------------------------
__global__ void __launch_bounds__(384) hd_main(float* __restrict__ out) {
    int blk = blockIdx.x;
    int chunk = blk % NCHUNK, dir = (blk / NCHUNK) & 1, img = blk / (2 * NCHUNK);
    int sset = dir, tset = dir ^ 1;
    int y0 = chunk * RPB;

    __shared__ unsigned tcm[HW * NCW];   // target column masks
    __shared__ unsigned scm[HW * NCW];   // source column masks
    __shared__ int      Gs[RPB * HW];    // column EDT for the 8 rows
    __shared__ int      smax;            // block running max
    __shared__ int      last_flag;

    int tid = threadIdx.x;
    // wide coalesced mask loads (288 words each => 72 uint4 each)
    if (tid < 72)
        ((uint4*)tcm)[tid] = ((const uint4*)g_cm[tset][img])[tid];
    else if (tid < 144)
        ((uint4*)scm)[tid - 72] = ((const uint4*)g_cm[sset][img])[tid - 72];
    if (tid == 0) smax = 0;
    __syncthreads();

    // column EDT for the block's 8 rows: 2 pixels per thread via bit scans
#pragma unroll
    for (int k = 0; k < 2; k++) {
        int p = tid + k * 384;
        int r = p / HW, x = p - r * HW;
        int y = y0 + r;
        unsigned c0 = tcm[x * 3], c1 = tcm[x * 3 + 1], c2 = tcm[x * 3 + 2];
        int w = y >> 5, b = y & 31;
        unsigned lowm = (2u << b) - 1u;
        unsigned him  = 0xffffffffu << b;

        unsigned m0 = (w == 0) ? (c0 & him) : 0u;
        unsigned m1 = (w < 1) ? c1 : ((w == 1) ? (c1 & him) : 0u);
        unsigned m2 = (w < 2) ? c2 : (c2 & him);
        int i2 = m2 ? 64 + __ffs(m2) - 1 : (1 << 14);
        int i1 = m1 ? 32 + __ffs(m1) - 1 : i2;
        int lo = m0 ? __ffs(m0) - 1 : i1;
        int dd = lo - y;

        unsigned h0 = (w == 0) ? (c0 & lowm) : c0;
        unsigned h1 = (w < 1) ? 0u : ((w == 1) ? (c1 & lowm) : c1);
        unsigned h2 = (w < 2) ? 0u : (c2 & lowm);
        int j0 = h0 ? 31 - __clz(h0) : -(1 << 14);
        int j1 = h1 ? 63 - __clz(h1) : j0;
        int hi = h2 ? 95 - __clz(h2) : j1;
        int du = y - hi;

        int d = min(dd, du);
        Gs[r * HW + x] = min(d * d, G_INF);
    }
    __syncthreads();

    int cntT = g_cntp[tset][img][0] + g_cntp[tset][img][1] + g_cntp[tset][img][2];

    if (cntT > 0) {
        // pruned windowed scan, only over source-masked pixels
#pragma unroll
        for (int k = 0; k < 2; k++) {
            int p = tid + k * 384;
            int r = p / HW, x = p - r * HW;
            int y = y0 + r;
            if (!((scm[x * 3 + (y >> 5)] >> (y & 31)) & 1)) continue;

            const int* Gr = &Gs[r * HW];
            int best = Gr[x];
            int s = smax;                 // stale read: pruning only
            if (best <= s) continue;      // D^2(x) <= G[x] <= smax
            for (int kk = 1; kk < HW && kk * kk < best; kk++) {
                int q = kk * kk;
                int xl = x - kk, xr = x + kk;
                if (xl >= 0) best = min(best, Gr[xl] + q);
                if (xr < HW) best = min(best, Gr[xr] + q);
                if (best <= s) break;     // can't raise the max anymore
            }
            if (best > s) atomicMax(&smax, best);
        }
    } else {
        // target empty: directed result = diameter of source set
        // (never taken for these inputs; kept for faithfulness)
        int lmax = 0;
        for (int p = tid; p < RPB * HW; p += 384) {
            int y = y0 + p / HW, x = p % HW;
            if (!((scm[x * 3 + (y >> 5)] >> (y & 31)) & 1)) continue;
            for (int q = 0; q < NPIX; q++) {
                int qy = q / HW, qx = q - qy * HW;
                if ((scm[qx * 3 + (qy >> 5)] >> (qy & 31)) & 1) {
                    int dy = y - qy, dx = x - qx;
                    lmax = max(lmax, dy * dy + dx * dx);
                }
            }
        }
        if (lmax > 0) atomicMax(&smax, lmax);
    }

    __syncthreads();
    if (tid == 0) atomicMax(&g_r[img][dir], smax);

    // fused final: last block computes the batch mean
    __syncthreads();
    if (tid == 0) {
        __threadfence();
        unsigned t = atomicAdd(&g_done, 1u);
        last_flag = (t == MAIN_BLOCKS - 1);
    }
    __syncthreads();
    if (last_flag && tid == 0) {
        __threadfence();
        float sum = 0.f;
        for (int i = 0; i < NB; i++)
            sum += sqrtf((float)max(g_r[i][0], g_r[i][1]));
        out[0] = sum * (1.0f / NB);
    }
}

extern "C" void kernel_launch(void* const* d_in, const int* in_sizes, int n_in,
                              void* d_out, int out_size) {
    const float* pred = (const float*)d_in[0];
    const float* targ = (const float*)d_in[1];

    hd_masks<<<96, 256>>>(pred, targ);
    hd_main<<<MAIN_BLOCKS, 384>>>((float*)d_out);
}